// round 9
// baseline (speedup 1.0000x reference)
#include <cuda_runtime.h>
#include <cuda_bf16.h>
#include <cstdint>

// ============================================================================
// tcgen05 availability guard (arch-specific "a" features). The plain
// compute_103 PTX pass compiles the FP32 fallback instead.
// ============================================================================
#if defined(__CUDA_ARCH_FEAT_SM103_ALL) || defined(__CUDA_ARCH_FEAT_SM100_ALL) || \
    defined(__CUDA_ARCH_FEAT_SM101_ALL) || defined(__CUDA_ARCH_SPECIFIC__)
#define TC_OK 1
#else
#define TC_OK 0
#endif

// ============================================================================
// Problem constants
// ============================================================================
#define NVOX 150000
#define CCH 256
#define TILE_M 128
#define NTILES ((NVOX + TILE_M - 1) / TILE_M)   // 1172
#define NCHUNKS 36                               // 3 axes * 3 taps * 4 (K=64 chunks)

// SMEM layout (tcgen05 path)
#define SMEM_TMEMPTR 0
#define SMEM_FREE    16                 // 4 x 8B (stage free <- MMA commit)
#define SMEM_BFULL   48                 // 4 x 8B (B tile arrived, tx)
#define SMEM_AFULL   80                 // 4 x 8B (A tile arrived, 16 warp arrivals)
#define SMEM_EPI     112                // 1 x 8B (epilogue TMEM reads done, 16)
#define SMEM_GB      128                // 6*256*4 = 6144 B
#define SMEM_STAGE   8192
#define STAGE_BYTES  49152              // A 16KB @ +0, B 32KB @ +16384
#define SMEM_BYTES   (8192 + 4 * STAGE_BYTES)   // 204800

// idesc: dtype=F32(bit4) | atype=BF16(bit7) | btype=BF16(bit10) | (N/8)<<17 | (M/16)<<24
#define MMA_IDESC 0x08400490u

// Pre-swizzled bf16 weight image: [3 axes][12 chunks] x (256 rows x 64 K) SW128
__device__ __align__(16) unsigned char g_Bimg[3 * 12 * 32768];
// bf16 precast of feats: [NVOX][256] bf16 = 76.8 MB (fits L2)
__device__ __align__(16) unsigned char g_featsBf[(size_t)NVOX * 512];

// ============================================================================
// Helpers
// ============================================================================
__device__ __forceinline__ uint32_t smem_u32(const void* p) {
    uint32_t a;
    asm("{ .reg .u64 t; cvta.to.shared.u64 t, %1; cvt.u32.u64 %0, t; }"
        : "=r"(a) : "l"(p));
    return a;
}

#define SW128(o) ((o) ^ (((o) >> 3) & 0x70))

static constexpr uint64_t SMEM_DESC_BASE_SW128 =
    (uint64_t(2) << 61) | (uint64_t(1) << 46) | (uint64_t(64) << 32) | (uint64_t(1) << 16);
#define MAKE_SMEM_DESC(base_addr) \
    (SMEM_DESC_BASE_SW128 | ((uint64_t)((base_addr) >> 4) & 0x3FFF))

__device__ __forceinline__ uint32_t pack_bf16x2(float a, float b) {
    __nv_bfloat162 h = __floats2bfloat162_rn(a, b);
    return *reinterpret_cast<uint32_t*>(&h);
}

#if TC_OK
__device__ __forceinline__ uint32_t elect_one() {
    uint32_t p;
    asm volatile("{ .reg .pred p; elect.sync _|p, 0xFFFFFFFF; selp.b32 %0, 1, 0, p; }"
                 : "=r"(p));
    return p;
}

#define TCGEN05_ALLOC(smem_result_addr, nCols) \
    asm volatile("tcgen05.alloc.cta_group::1.sync.aligned.shared::cta.b32 [%0], %1;" \
                 :: "r"((uint32_t)(smem_result_addr)), "r"((uint32_t)(nCols)) : "memory")
#define TCGEN05_DEALLOC(tmem_addr, nCols) \
    asm volatile("tcgen05.dealloc.cta_group::1.sync.aligned.b32 %0, %1;" \
                 :: "r"(tmem_addr), "r"((uint32_t)(nCols)))
#define TCGEN05_RELINQUISH() \
    asm volatile("tcgen05.relinquish_alloc_permit.cta_group::1.sync.aligned;")
#define TCGEN05_COMMIT(mbar_smem_addr) \
    asm volatile("tcgen05.commit.cta_group::1.mbarrier::arrive::one.shared::cluster.b64 [%0];" \
                 :: "r"((uint32_t)(mbar_smem_addr)) : "memory")
#define TCGEN05_WAIT_LD() \
    asm volatile("tcgen05.wait::ld.sync.aligned;" ::: "memory")
#define TCGEN05_FENCE_BEFORE() \
    asm volatile("tcgen05.fence::before_thread_sync;" ::: "memory")
#define TCGEN05_FENCE_AFTER() \
    asm volatile("tcgen05.fence::after_thread_sync;" ::: "memory")
#define FENCE_PROXY_ASYNC() \
    asm volatile("fence.proxy.async.shared::cta;" ::: "memory")

#define MBARRIER_INIT(mbar_smem_addr, count) \
    asm volatile("mbarrier.init.shared.b64 [%0], %1;" \
                 :: "r"((uint32_t)(mbar_smem_addr)), "r"((uint32_t)(count)) : "memory")

#define MBARRIER_ARRIVE(mbar_smem_addr) \
    asm volatile("mbarrier.arrive.release.cta.shared::cta.b64 _, [%0];" \
                 :: "r"((uint32_t)(mbar_smem_addr)) : "memory")

#define MBARRIER_EXPECT_TX(mbar_smem_addr, tx_bytes) \
    asm volatile("mbarrier.arrive.expect_tx.shared.b64 _, [%0], %1;" \
                 :: "r"((uint32_t)(mbar_smem_addr)), "r"((uint32_t)(tx_bytes)) : "memory")

#define MBARRIER_WAIT_PARITY(mbar_smem_addr, phase_parity) do { \
    uint32_t _mbar = (uint32_t)(mbar_smem_addr); \
    uint32_t _parity = (uint32_t)(phase_parity); \
    uint32_t _done; \
    asm volatile( \
        "{\n\t" \
        ".reg .pred p;\n\t" \
        "mbarrier.try_wait.parity.acquire.cta.shared::cta.b64 p, [%1], %2;\n\t" \
        "selp.b32 %0, 1, 0, p;\n\t" \
        "}" \
        : "=r"(_done) : "r"(_mbar), "r"(_parity) : "memory"); \
    if (!_done) { \
        asm volatile( \
            "{\n\t" \
            ".reg .pred P1;\n\t" \
            "WAIT_LOOP_%=:\n\t" \
            "mbarrier.try_wait.parity.acquire.cta.shared::cta.b64 P1, [%0], %1, 0x989680;\n\t" \
            "@P1 bra.uni WAIT_DONE_%=;\n\t" \
            "bra.uni WAIT_LOOP_%=;\n\t" \
            "WAIT_DONE_%=:\n\t" \
            "}" \
            :: "r"(_mbar), "r"(_parity) : "memory"); \
    } \
} while (0)

#define TCGEN05_LD_32X32B_X16(r, tmem_addr) \
    asm volatile( \
        "tcgen05.ld.sync.aligned.32x32b.x16.b32 " \
        "{%0, %1, %2, %3, %4, %5, %6, %7, " \
        " %8, %9, %10, %11, %12, %13, %14, %15}, [%16];" \
        : "=r"((r)[0]),  "=r"((r)[1]),  "=r"((r)[2]),  "=r"((r)[3]), \
          "=r"((r)[4]),  "=r"((r)[5]),  "=r"((r)[6]),  "=r"((r)[7]), \
          "=r"((r)[8]),  "=r"((r)[9]),  "=r"((r)[10]), "=r"((r)[11]), \
          "=r"((r)[12]), "=r"((r)[13]), "=r"((r)[14]), "=r"((r)[15]) \
        : "r"(tmem_addr))

__device__ __forceinline__ void mma_f16_ss(uint32_t d_tmem, uint64_t a_desc,
                                           uint64_t b_desc, uint32_t idesc,
                                           uint32_t enable_d) {
    asm volatile(
        "{\n\t"
        ".reg .pred p;\n\t"
        "setp.ne.u32 p, %5, 0;\n\t"
        "tcgen05.mma.cta_group::1.kind::f16 [%0], %1, %2, %3, {%4, %4, %4, %4}, p;\n\t"
        "}"
        :: "r"(d_tmem), "l"(a_desc), "l"(b_desc), "r"(idesc), "r"(0u), "r"(enable_d)
        : "memory");
}

// 16B async copy with zero-fill control (src_size = 16 or 0)
#define CP_ASYNC16(dst, src, sz) \
    asm volatile("cp.async.cg.shared.global [%0], [%1], 16, %2;" \
                 :: "r"((uint32_t)(dst)), "l"(src), "r"((uint32_t)(sz)) : "memory")
#define CP_COMMIT() asm volatile("cp.async.commit_group;" ::: "memory")
#define CP_WAIT_GROUP(N) asm volatile("cp.async.wait_group %0;" :: "n"(N) : "memory")

// bulk async copy gmem -> smem, completion via mbarrier tx-bytes
#define CP_BULK(dst, src, bytes, mbar) \
    asm volatile("cp.async.bulk.shared::cluster.global.mbarrier::complete_tx::bytes " \
                 "[%0], [%1], %2, [%3];" \
                 :: "r"((uint32_t)(dst)), "l"(src), "r"((uint32_t)(bytes)), \
                    "r"((uint32_t)(mbar)) : "memory")
#endif  // TC_OK

// ============================================================================
// Prep 1: fp32 weights -> bf16 SW128 B image
// ============================================================================
__global__ void prep_weights_kernel(const float* __restrict__ w1,
                                    const float* __restrict__ w2,
                                    const float* __restrict__ w3) {
#if TC_OK
    int id = blockIdx.x * 256 + threadIdx.x;
    if (id >= 3 * 196608) return;
    int axis = id / 196608;
    int r = id - axis * 196608;          // tap*65536 + c*256 + d
    const float* w = (axis == 0) ? w1 : ((axis == 1) ? w2 : w3);
    float v = w[r];
    int tap = r >> 16;
    int c = (r >> 8) & 255;
    int d = r & 255;
    int kk = tap * 256 + c;
    int q  = kk >> 6;
    int kc = kk & 63;
    int off = d * 128 + kc * 2;
    *reinterpret_cast<__nv_bfloat16*>(g_Bimg + (axis * 12 + q) * 32768 + SW128(off)) =
        __float2bfloat16(v);
#endif
}

// ============================================================================
// Prep 2: feats fp32 -> bf16 image (16 floats / thread)
// ============================================================================
__global__ void prep_feats_kernel(const float* __restrict__ feats) {
#if TC_OK
    int t = blockIdx.x * 256 + threadIdx.x;
    if (t >= (NVOX * CCH) / 16) return;
    const float4* src = reinterpret_cast<const float4*>(feats) + (size_t)t * 4;
    float4 a = src[0], b = src[1], c = src[2], d = src[3];
    uint4 r0, r1;
    r0.x = pack_bf16x2(a.x, a.y); r0.y = pack_bf16x2(a.z, a.w);
    r0.z = pack_bf16x2(b.x, b.y); r0.w = pack_bf16x2(b.z, b.w);
    r1.x = pack_bf16x2(c.x, c.y); r1.y = pack_bf16x2(c.z, c.w);
    r1.z = pack_bf16x2(d.x, d.y); r1.w = pack_bf16x2(d.z, d.w);
    uint4* dst = reinterpret_cast<uint4*>(g_featsBf) + (size_t)t * 2;
    dst[0] = r0;
    dst[1] = r1;
#endif
}

// ============================================================================
// Main kernel: one 128-voxel tile per CTA, 512 threads.
// Warp-decoupled 4-stage pipeline: NO per-chunk __syncthreads.
//  - every warp: produce(g+3) [FREE wait], wait_group, fence, elect-arrive AFULL
//  - warp0 elect: wait AFULL(16)+BFULL(tx), issue 4 MMAs, commit -> FREE
//  - per-axis epilogue ordered by EPI mbarrier (16 arrivals), waited by the
//    next axis's first MMA.
// ============================================================================
__global__ __launch_bounds__(512, 1)
void recon_main_kernel(const float* __restrict__ feats,
                       const float* __restrict__ w1, const float* __restrict__ w2,
                       const float* __restrict__ w3,
                       const float* __restrict__ g1, const float* __restrict__ b1,
                       const float* __restrict__ g2, const float* __restrict__ b2,
                       const float* __restrict__ g3, const float* __restrict__ b3,
                       const int* __restrict__ nx, const int* __restrict__ ny,
                       const int* __restrict__ nz,
                       float* __restrict__ out) {
    extern __shared__ __align__(1024) unsigned char smem[];
    int tid = threadIdx.x;
    int warp = tid >> 5;
    int lane = tid & 31;
    int m0 = blockIdx.x * TILE_M;

    // A-loader mapping: 4 threads per row, each 32B (2 x 16B cp.async)
    int arow = tid >> 2;
    int aseg = tid & 3;
    int agm = m0 + arow;
    bool rowvalid = agm < NVOX;

    // epilogue mapping: warp w -> rows (w&3)*32+lane, cols [(w>>2)*64, +64)
    int erow = (warp & 3) * 32 + lane;
    int colb = (warp >> 2) * 64;
    int egm = m0 + erow;

    float s[64];
#pragma unroll
    for (int i = 0; i < 64; i++) s[i] = 0.0f;

    const float RS = rsqrtf(1.00001f);

#if TC_OK
    uint32_t sb = smem_u32(smem);

    float* gb = reinterpret_cast<float*>(smem + SMEM_GB);
    if (tid < 256) {
        gb[0 * 256 + tid] = g1[tid];
        gb[1 * 256 + tid] = b1[tid];
        gb[2 * 256 + tid] = g2[tid];
        gb[3 * 256 + tid] = b2[tid];
        gb[4 * 256 + tid] = g3[tid];
        gb[5 * 256 + tid] = b3[tid];
    }
    if (warp == 0) TCGEN05_ALLOC(sb + SMEM_TMEMPTR, 256);
    if (tid == 0) {
#pragma unroll
        for (int i = 0; i < 4; i++) {
            MBARRIER_INIT(sb + SMEM_FREE + 8 * i, 1);
            MBARRIER_INIT(sb + SMEM_BFULL + 8 * i, 1);
            MBARRIER_INIT(sb + SMEM_AFULL + 8 * i, 16);
        }
        MBARRIER_INIT(sb + SMEM_EPI, 16);
    }
    __syncthreads();
    uint32_t tmem;
    asm volatile("ld.shared.b32 %0, [%1];" : "=r"(tmem) : "r"(sb + SMEM_TMEMPTR));

    // producer: issue all async loads for chunk p into stage p&3
    auto produce = [&](int p) {
        int st = p & 3;
        if (p >= 4)
            MBARRIER_WAIT_PARITY(sb + SMEM_FREE + 8 * st, ((p >> 2) - 1) & 1);
        int axis_p = p / 12;
        int cidx = p - axis_p * 12;
        int tap = cidx >> 2;
        const int* nb = (axis_p == 0) ? nx : ((axis_p == 1) ? ny : nz);
        uint32_t a_base = sb + SMEM_STAGE + (uint32_t)st * STAGE_BYTES;
        // B: one bulk copy of the 32KB pre-swizzled tile (warp0 elect)
        if (warp == 0) {
            if (elect_one()) {
                uint32_t bm = sb + SMEM_BFULL + 8 * st;
                MBARRIER_EXPECT_TX(bm, 32768u);
                const char* bsrc = reinterpret_cast<const char*>(g_Bimg) +
                                   (size_t)(axis_p * 12 + cidx) * 32768;
                CP_BULK(a_base + 16384, bsrc, 32768u, bm);
            }
        }
        // A: gather bf16 row chunk, 2 x 16B per thread (zero-fill if inactive)
        int idx = rowvalid ? __ldg(&nb[agm * 3 + tap]) : -1;
        int cbase = ((cidx & 3) << 6) + (aseg << 4);
        const char* asrc = reinterpret_cast<const char*>(g_featsBf) +
                           (size_t)(idx < 0 ? 0 : idx) * 512 + (size_t)cbase * 2;
        uint32_t sz = (idx >= 0) ? 16u : 0u;
        uint32_t bo = (uint32_t)(arow * 128 + aseg * 32);
        CP_ASYNC16(a_base + SW128(bo), asrc, sz);
        CP_ASYNC16(a_base + SW128(bo + 16), asrc + 16, sz);
        CP_COMMIT();
    };

    // prime 3 chunks
    produce(0); produce(1); produce(2);

    for (int g = 0; g < NCHUNKS; g++) {
        int axis_g = g / 12;
        int cidx = g - axis_g * 12;
        int st = g & 3;
        int ph = (g >> 2) & 1;

        if (g + 3 < NCHUNKS) produce(g + 3);

        // retire chunk g's A group (issued 3 iters ago; after produce, pending
        // groups newer than g: min(3, NCHUNKS-1-g))
        if (g <= NCHUNKS - 4)      CP_WAIT_GROUP(3);
        else if (g == NCHUNKS - 3) CP_WAIT_GROUP(2);
        else if (g == NCHUNKS - 2) CP_WAIT_GROUP(1);
        else                       CP_WAIT_GROUP(0);
        FENCE_PROXY_ASYNC();
        if (elect_one()) MBARRIER_ARRIVE(sb + SMEM_AFULL + 8 * st);

        // MMA issue (warp0 elect only; other warps run ahead to next produce)
        if (warp == 0) {
            if (elect_one()) {
                MBARRIER_WAIT_PARITY(sb + SMEM_AFULL + 8 * st, ph);
                MBARRIER_WAIT_PARITY(sb + SMEM_BFULL + 8 * st, ph);
                if (cidx == 0) {
                    // axis > 0: previous axis's TMEM reads must be done
                    if (axis_g > 0)
                        MBARRIER_WAIT_PARITY(sb + SMEM_EPI, (axis_g - 1) & 1);
                    TCGEN05_FENCE_AFTER();
                }
                uint32_t a_base = sb + SMEM_STAGE + (uint32_t)st * STAGE_BYTES;
                uint64_t ad = MAKE_SMEM_DESC(a_base);
                uint64_t bd = MAKE_SMEM_DESC(a_base + 16384);
#pragma unroll
                for (int k = 0; k < 4; k++)
                    mma_f16_ss(tmem, ad + k * 2, bd + k * 2, MMA_IDESC,
                               (uint32_t)((cidx > 0) || (k > 0)));
                TCGEN05_COMMIT(sb + SMEM_FREE + 8 * st);
            }
        }

        if (cidx == 11) {
            // axis complete: all warps wait last MMA, BN+sigmoid accumulate
            MBARRIER_WAIT_PARITY(sb + SMEM_FREE + 8 * st, ph);
            TCGEN05_FENCE_AFTER();
            const float* gptr = gb + axis_g * 512;
#pragma unroll
            for (int i = 0; i < 4; i++) {
                uint32_t t[16];
                TCGEN05_LD_32X32B_X16(t, tmem + colb + i * 16);
                TCGEN05_WAIT_LD();
#pragma unroll
                for (int j = 0; j < 16; j++) {
                    int c = colb + i * 16 + j;
                    float y = __uint_as_float(t[j]);
                    float v = fmaf(y, gptr[c] * RS, gptr[256 + c]);
                    s[i * 16 + j] += 1.0f / (1.0f + __expf(-v));
                }
            }
            TCGEN05_FENCE_BEFORE();
            if (elect_one()) MBARRIER_ARRIVE(sb + SMEM_EPI);
        }
    }

    // final: out = s * feats (fp32)
    if (egm < NVOX) {
        const float4* fr = reinterpret_cast<const float4*>(
            feats + (size_t)egm * CCH + colb);
        float4* orow = reinterpret_cast<float4*>(
            out + (size_t)egm * CCH + colb);
#pragma unroll
        for (int i = 0; i < 16; i++) {
            float4 f = fr[i];
            float4 r;
            r.x = f.x * s[i * 4 + 0];
            r.y = f.y * s[i * 4 + 1];
            r.z = f.z * s[i * 4 + 2];
            r.w = f.w * s[i * 4 + 3];
            orow[i] = r;
        }
    }
    __syncthreads();
    if (warp == 0) {
        TCGEN05_RELINQUISH();
        TCGEN05_DEALLOC(tmem, 256);
    }

#else
    // ------------------------------------------------------------------
    // Portable FP32 fallback (non-"a" PTX pass only)
    // ------------------------------------------------------------------
    float* a_tile = reinterpret_cast<float*>(smem);            // [128][65]
    float* w_tile = reinterpret_cast<float*>(smem + 33280);    // [64][256]

    for (int axis = 0; axis < 3; axis++) {
        const int* nb = (axis == 0) ? nx : ((axis == 1) ? ny : nz);
        const float* w = (axis == 0) ? w1 : ((axis == 1) ? w2 : w3);
        const float* gg = (axis == 0) ? g1 : ((axis == 1) ? g2 : g3);
        const float* bb = (axis == 0) ? b1 : ((axis == 1) ? b2 : b3);

        float y[64];
#pragma unroll
        for (int i = 0; i < 64; i++) y[i] = 0.0f;

        for (int tap = 0; tap < 3; tap++) {
            int idx = rowvalid ? __ldg(&nb[agm * 3 + tap]) : -1;
            for (int kc = 0; kc < 4; kc++) {
                int kbase = kc * 64;
                {
                    float v[16];
                    if (idx >= 0) {
                        const float4* src = reinterpret_cast<const float4*>(
                            feats + (size_t)idx * CCH + kbase + aseg * 16);
#pragma unroll
                        for (int i = 0; i < 4; i++) {
                            float4 f = src[i];
                            v[i * 4 + 0] = f.x; v[i * 4 + 1] = f.y;
                            v[i * 4 + 2] = f.z; v[i * 4 + 3] = f.w;
                        }
                    } else {
#pragma unroll
                        for (int i = 0; i < 16; i++) v[i] = 0.0f;
                    }
#pragma unroll
                    for (int i = 0; i < 16; i++)
                        a_tile[arow * 65 + aseg * 16 + i] = v[i];
                }
                {
                    const float4* src = reinterpret_cast<const float4*>(
                        w + (size_t)tap * 65536 + (size_t)kbase * 256);
                    float4* dst = reinterpret_cast<float4*>(w_tile);
#pragma unroll
                    for (int i = 0; i < 8; i++) dst[tid + i * 512] = src[tid + i * 512];
                }
                __syncthreads();
                for (int k = 0; k < 64; k++) {
                    float ra = a_tile[erow * 65 + k];
                    const float4* wr = reinterpret_cast<const float4*>(
                        w_tile + k * 256 + colb);
#pragma unroll
                    for (int cc = 0; cc < 16; cc++) {
                        float4 wv = wr[cc];
                        y[cc * 4 + 0] = fmaf(ra, wv.x, y[cc * 4 + 0]);
                        y[cc * 4 + 1] = fmaf(ra, wv.y, y[cc * 4 + 1]);
                        y[cc * 4 + 2] = fmaf(ra, wv.z, y[cc * 4 + 2]);
                        y[cc * 4 + 3] = fmaf(ra, wv.w, y[cc * 4 + 3]);
                    }
                }
                __syncthreads();
            }
        }
#pragma unroll
        for (int i = 0; i < 64; i++) {
            int c = colb + i;
            float v = fmaf(y[i], __ldg(&gg[c]) * RS, __ldg(&bb[c]));
            s[i] += 1.0f / (1.0f + __expf(-v));
        }
    }

    if (egm < NVOX) {
        const float4* fr = reinterpret_cast<const float4*>(
            feats + (size_t)egm * CCH + colb);
        float4* orow = reinterpret_cast<float4*>(
            out + (size_t)egm * CCH + colb);
#pragma unroll
        for (int i = 0; i < 16; i++) {
            float4 f = fr[i];
            float4 r;
            r.x = f.x * s[i * 4 + 0];
            r.y = f.y * s[i * 4 + 1];
            r.z = f.z * s[i * 4 + 2];
            r.w = f.w * s[i * 4 + 3];
            orow[i] = r;
        }
    }
#endif  // TC_OK
}

// ============================================================================
// Launch
// ============================================================================
extern "C" void kernel_launch(void* const* d_in, const int* in_sizes, int n_in,
                              void* d_out, int out_size) {
    const float* feats = (const float*)d_in[0];
    const float* w1 = (const float*)d_in[1];
    const float* w2 = (const float*)d_in[2];
    const float* w3 = (const float*)d_in[3];
    const float* g1 = (const float*)d_in[4];
    const float* b1 = (const float*)d_in[5];
    const float* g2 = (const float*)d_in[6];
    const float* b2 = (const float*)d_in[7];
    const float* g3 = (const float*)d_in[8];
    const float* b3 = (const float*)d_in[9];
    const int* nx = (const int*)d_in[10];
    const int* ny = (const int*)d_in[11];
    const int* nz = (const int*)d_in[12];
    float* out = (float*)d_out;

    cudaFuncSetAttribute(recon_main_kernel,
                         cudaFuncAttributeMaxDynamicSharedMemorySize, SMEM_BYTES);

    prep_weights_kernel<<<(3 * 196608 + 255) / 256, 256>>>(w1, w2, w3);
    prep_feats_kernel<<<((NVOX * CCH / 16) + 255) / 256, 256>>>(feats);
    recon_main_kernel<<<NTILES, 512, SMEM_BYTES>>>(feats, w1, w2, w3,
                                                   g1, b1, g2, b2, g3, b3,
                                                   nx, ny, nz, out);
}

// round 10
// speedup vs baseline: 1.1204x; 1.1204x over previous
#include <cuda_runtime.h>
#include <cuda_bf16.h>
#include <cstdint>

// ============================================================================
// tcgen05 availability guard (arch-specific "a" features). The plain
// compute_103 PTX pass compiles the FP32 fallback instead.
// ============================================================================
#if defined(__CUDA_ARCH_FEAT_SM103_ALL) || defined(__CUDA_ARCH_FEAT_SM100_ALL) || \
    defined(__CUDA_ARCH_FEAT_SM101_ALL) || defined(__CUDA_ARCH_SPECIFIC__)
#define TC_OK 1
#else
#define TC_OK 0
#endif

// ============================================================================
// Problem constants
// ============================================================================
#define NVOX 150000
#define CCH 256
#define TILE_M 128
#define NTILES ((NVOX + TILE_M - 1) / TILE_M)   // 1172
#define NMACRO 18                                // 3 axes * 6 macro chunks (K=128)

// SMEM layout (tcgen05 path)
#define SMEM_TMEMPTR 0
#define SMEM_FREE    16                 // 2 x 8B (stage free <- MMA commit)
#define SMEM_BFULL   32                 // 2 x 8B (B tile arrived, tx)
#define SMEM_GB      64                 // 6*256*4 = 6144 B
#define SMEM_STAGE   8192
#define STAGE_BYTES  98304              // A: 2 x 16KB sub-tiles; B: 64KB @ +32768
#define SMEM_BYTES   (8192 + 2 * STAGE_BYTES)   // 204800

// idesc: dtype=F32(bit4) | atype=BF16(bit7) | btype=BF16(bit10) | (N/8)<<17 | (M/16)<<24
#define MMA_IDESC 0x08400490u

// Pre-swizzled bf16 weight image: [3 axes][12 chunks] x (256 rows x 64 K) SW128
__device__ __align__(16) unsigned char g_Bimg[3 * 12 * 32768];
// bf16 precast of feats: [NVOX][256] bf16 = 76.8 MB (fits L2)
__device__ __align__(16) unsigned char g_featsBf[(size_t)NVOX * 512];

#define PREP_W_IDS (3 * 196608)                  // 589824
#define PREP_F_IDS ((NVOX * CCH) / 16)           // 2400000
#define PREP_BLOCKS ((PREP_W_IDS + PREP_F_IDS + 255) / 256)

// ============================================================================
// Helpers
// ============================================================================
__device__ __forceinline__ uint32_t smem_u32(const void* p) {
    uint32_t a;
    asm("{ .reg .u64 t; cvta.to.shared.u64 t, %1; cvt.u32.u64 %0, t; }"
        : "=r"(a) : "l"(p));
    return a;
}

#define SW128(o) ((o) ^ (((o) >> 3) & 0x70))

static constexpr uint64_t SMEM_DESC_BASE_SW128 =
    (uint64_t(2) << 61) | (uint64_t(1) << 46) | (uint64_t(64) << 32) | (uint64_t(1) << 16);
#define MAKE_SMEM_DESC(base_addr) \
    (SMEM_DESC_BASE_SW128 | ((uint64_t)((base_addr) >> 4) & 0x3FFF))

__device__ __forceinline__ uint32_t pack_bf16x2(float a, float b) {
    __nv_bfloat162 h = __floats2bfloat162_rn(a, b);
    return *reinterpret_cast<uint32_t*>(&h);
}

#if TC_OK
__device__ __forceinline__ uint32_t elect_one() {
    uint32_t p;
    asm volatile("{ .reg .pred p; elect.sync _|p, 0xFFFFFFFF; selp.b32 %0, 1, 0, p; }"
                 : "=r"(p));
    return p;
}

#define TCGEN05_ALLOC(smem_result_addr, nCols) \
    asm volatile("tcgen05.alloc.cta_group::1.sync.aligned.shared::cta.b32 [%0], %1;" \
                 :: "r"((uint32_t)(smem_result_addr)), "r"((uint32_t)(nCols)) : "memory")
#define TCGEN05_DEALLOC(tmem_addr, nCols) \
    asm volatile("tcgen05.dealloc.cta_group::1.sync.aligned.b32 %0, %1;" \
                 :: "r"(tmem_addr), "r"((uint32_t)(nCols)))
#define TCGEN05_RELINQUISH() \
    asm volatile("tcgen05.relinquish_alloc_permit.cta_group::1.sync.aligned;")
#define TCGEN05_COMMIT(mbar_smem_addr) \
    asm volatile("tcgen05.commit.cta_group::1.mbarrier::arrive::one.shared::cluster.b64 [%0];" \
                 :: "r"((uint32_t)(mbar_smem_addr)) : "memory")
#define TCGEN05_WAIT_LD() \
    asm volatile("tcgen05.wait::ld.sync.aligned;" ::: "memory")
#define TCGEN05_FENCE_BEFORE() \
    asm volatile("tcgen05.fence::before_thread_sync;" ::: "memory")
#define TCGEN05_FENCE_AFTER() \
    asm volatile("tcgen05.fence::after_thread_sync;" ::: "memory")
#define FENCE_PROXY_ASYNC() \
    asm volatile("fence.proxy.async.shared::cta;" ::: "memory")

#define MBARRIER_INIT(mbar_smem_addr, count) \
    asm volatile("mbarrier.init.shared.b64 [%0], %1;" \
                 :: "r"((uint32_t)(mbar_smem_addr)), "r"((uint32_t)(count)) : "memory")

#define MBARRIER_EXPECT_TX(mbar_smem_addr, tx_bytes) \
    asm volatile("mbarrier.arrive.expect_tx.shared.b64 _, [%0], %1;" \
                 :: "r"((uint32_t)(mbar_smem_addr)), "r"((uint32_t)(tx_bytes)) : "memory")

#define MBARRIER_WAIT_PARITY(mbar_smem_addr, phase_parity) do { \
    uint32_t _mbar = (uint32_t)(mbar_smem_addr); \
    uint32_t _parity = (uint32_t)(phase_parity); \
    uint32_t _done; \
    asm volatile( \
        "{\n\t" \
        ".reg .pred p;\n\t" \
        "mbarrier.try_wait.parity.acquire.cta.shared::cta.b64 p, [%1], %2;\n\t" \
        "selp.b32 %0, 1, 0, p;\n\t" \
        "}" \
        : "=r"(_done) : "r"(_mbar), "r"(_parity) : "memory"); \
    if (!_done) { \
        asm volatile( \
            "{\n\t" \
            ".reg .pred P1;\n\t" \
            "WAIT_LOOP_%=:\n\t" \
            "mbarrier.try_wait.parity.acquire.cta.shared::cta.b64 P1, [%0], %1, 0x989680;\n\t" \
            "@P1 bra.uni WAIT_DONE_%=;\n\t" \
            "bra.uni WAIT_LOOP_%=;\n\t" \
            "WAIT_DONE_%=:\n\t" \
            "}" \
            :: "r"(_mbar), "r"(_parity) : "memory"); \
    } \
} while (0)

#define TCGEN05_LD_32X32B_X16(r, tmem_addr) \
    asm volatile( \
        "tcgen05.ld.sync.aligned.32x32b.x16.b32 " \
        "{%0, %1, %2, %3, %4, %5, %6, %7, " \
        " %8, %9, %10, %11, %12, %13, %14, %15}, [%16];" \
        : "=r"((r)[0]),  "=r"((r)[1]),  "=r"((r)[2]),  "=r"((r)[3]), \
          "=r"((r)[4]),  "=r"((r)[5]),  "=r"((r)[6]),  "=r"((r)[7]), \
          "=r"((r)[8]),  "=r"((r)[9]),  "=r"((r)[10]), "=r"((r)[11]), \
          "=r"((r)[12]), "=r"((r)[13]), "=r"((r)[14]), "=r"((r)[15]) \
        : "r"(tmem_addr))

__device__ __forceinline__ void mma_f16_ss(uint32_t d_tmem, uint64_t a_desc,
                                           uint64_t b_desc, uint32_t idesc,
                                           uint32_t enable_d) {
    asm volatile(
        "{\n\t"
        ".reg .pred p;\n\t"
        "setp.ne.u32 p, %5, 0;\n\t"
        "tcgen05.mma.cta_group::1.kind::f16 [%0], %1, %2, %3, {%4, %4, %4, %4}, p;\n\t"
        "}"
        :: "r"(d_tmem), "l"(a_desc), "l"(b_desc), "r"(idesc), "r"(0u), "r"(enable_d)
        : "memory");
}

// 16B async copy with zero-fill control (src_size = 16 or 0)
#define CP_ASYNC16(dst, src, sz) \
    asm volatile("cp.async.cg.shared.global [%0], [%1], 16, %2;" \
                 :: "r"((uint32_t)(dst)), "l"(src), "r"((uint32_t)(sz)) : "memory")
#define CP_COMMIT() asm volatile("cp.async.commit_group;" ::: "memory")
#define CP_WAIT_GROUP(N) asm volatile("cp.async.wait_group %0;" :: "n"(N) : "memory")

// bulk async copy gmem -> smem, completion via mbarrier tx-bytes
#define CP_BULK(dst, src, bytes, mbar) \
    asm volatile("cp.async.bulk.shared::cluster.global.mbarrier::complete_tx::bytes " \
                 "[%0], [%1], %2, [%3];" \
                 :: "r"((uint32_t)(dst)), "l"(src), "r"((uint32_t)(bytes)), \
                    "r"((uint32_t)(mbar)) : "memory")
#endif  // TC_OK

// ============================================================================
// Merged prep kernel: weights -> bf16 SW128 B image AND feats -> bf16 image
// (single launch keeps the launch pattern at 2/call so ncu captures main)
// ============================================================================
__global__ void prep_all_kernel(const float* __restrict__ w1,
                                const float* __restrict__ w2,
                                const float* __restrict__ w3,
                                const float* __restrict__ feats) {
#if TC_OK
    int id = blockIdx.x * 256 + threadIdx.x;
    if (id < PREP_W_IDS) {
        int axis = id / 196608;
        int r = id - axis * 196608;          // tap*65536 + c*256 + d
        const float* w = (axis == 0) ? w1 : ((axis == 1) ? w2 : w3);
        float v = w[r];
        int tap = r >> 16;
        int c = (r >> 8) & 255;
        int d = r & 255;
        int kk = tap * 256 + c;
        int q  = kk >> 6;
        int kc = kk & 63;
        int off = d * 128 + kc * 2;
        *reinterpret_cast<__nv_bfloat16*>(g_Bimg + (axis * 12 + q) * 32768 + SW128(off)) =
            __float2bfloat16(v);
    } else {
        int t = id - PREP_W_IDS;
        if (t >= PREP_F_IDS) return;
        const float4* src = reinterpret_cast<const float4*>(feats) + (size_t)t * 4;
        float4 a = src[0], b = src[1], c = src[2], d = src[3];
        uint4 r0, r1;
        r0.x = pack_bf16x2(a.x, a.y); r0.y = pack_bf16x2(a.z, a.w);
        r0.z = pack_bf16x2(b.x, b.y); r0.w = pack_bf16x2(b.z, b.w);
        r1.x = pack_bf16x2(c.x, c.y); r1.y = pack_bf16x2(c.z, c.w);
        r1.z = pack_bf16x2(d.x, d.y); r1.w = pack_bf16x2(d.z, d.w);
        uint4* dst = reinterpret_cast<uint4*>(g_featsBf) + (size_t)t * 2;
        dst[0] = r0;
        dst[1] = r1;
    }
#endif
}

// ============================================================================
// Main kernel: one 128-voxel tile per CTA, 512 threads.
// 18 macro chunks (K=128, 8 MMAs each), 2-stage pipeline (96KB/stage),
// R7-style __syncthreads structure. Neighbor indices prefetched once.
// ============================================================================
__global__ __launch_bounds__(512, 1)
void recon_main_kernel(const float* __restrict__ feats,
                       const float* __restrict__ w1, const float* __restrict__ w2,
                       const float* __restrict__ w3,
                       const float* __restrict__ g1, const float* __restrict__ b1,
                       const float* __restrict__ g2, const float* __restrict__ b2,
                       const float* __restrict__ g3, const float* __restrict__ b3,
                       const int* __restrict__ nx, const int* __restrict__ ny,
                       const int* __restrict__ nz,
                       float* __restrict__ out) {
    extern __shared__ __align__(1024) unsigned char smem[];
    int tid = threadIdx.x;
    int warp = tid >> 5;
    int lane = tid & 31;
    int m0 = blockIdx.x * TILE_M;

    // A-loader mapping: 4 threads per row, each 32B per K64 sub-chunk
    int arow = tid >> 2;
    int aseg = tid & 3;
    int agm = m0 + arow;
    bool rowvalid = agm < NVOX;

    // epilogue mapping: warp w -> rows (w&3)*32+lane, cols [(w>>2)*64, +64)
    int erow = (warp & 3) * 32 + lane;
    int colb = (warp >> 2) * 64;
    int egm = m0 + erow;

    float s[64];
#pragma unroll
    for (int i = 0; i < 64; i++) s[i] = 0.0f;

    const float RS = rsqrtf(1.00001f);

#if TC_OK
    uint32_t sb = smem_u32(smem);

    // ---- prefetch ALL 9 neighbor indices for this thread's row (off loop) ----
    int nidx[9];
    {
        const int* nbs[3] = { nx, ny, nz };
#pragma unroll
        for (int a = 0; a < 3; a++)
#pragma unroll
            for (int tp = 0; tp < 3; tp++)
                nidx[a * 3 + tp] = rowvalid ? __ldg(&nbs[a][agm * 3 + tp]) : -1;
    }

    float* gb = reinterpret_cast<float*>(smem + SMEM_GB);
    if (tid < 256) {
        gb[0 * 256 + tid] = g1[tid];
        gb[1 * 256 + tid] = b1[tid];
        gb[2 * 256 + tid] = g2[tid];
        gb[3 * 256 + tid] = b2[tid];
        gb[4 * 256 + tid] = g3[tid];
        gb[5 * 256 + tid] = b3[tid];
    }
    if (warp == 0) TCGEN05_ALLOC(sb + SMEM_TMEMPTR, 256);
    if (tid == 0) {
#pragma unroll
        for (int i = 0; i < 2; i++) {
            MBARRIER_INIT(sb + SMEM_FREE + 8 * i, 1);
            MBARRIER_INIT(sb + SMEM_BFULL + 8 * i, 1);
        }
    }
    __syncthreads();
    uint32_t tmem;
    asm volatile("ld.shared.b32 %0, [%1];" : "=r"(tmem) : "r"(sb + SMEM_TMEMPTR));

    // producer: issue all async loads for macro chunk p into stage p&1
    auto produce = [&](int p) {
        int st = p & 1;
        if (p >= 2)   // stage last used by chunk p-2; freed by its MMA commit
            MBARRIER_WAIT_PARITY(sb + SMEM_FREE + 8 * st, ((p >> 1) - 1) & 1);
        int axis_p = p / 6;
        int h = p - axis_p * 6;            // macro chunk within axis (0..5)
        uint32_t a_base = sb + SMEM_STAGE + (uint32_t)st * STAGE_BYTES;
        // B: one 64KB bulk (two consecutive 32KB pre-swizzled K64 tiles)
        if (warp == 0) {
            if (elect_one()) {
                uint32_t bm = sb + SMEM_BFULL + 8 * st;
                MBARRIER_EXPECT_TX(bm, 65536u);
                const char* bsrc = reinterpret_cast<const char*>(g_Bimg) +
                                   (size_t)(axis_p * 12 + 2 * h) * 32768;
                CP_BULK(a_base + 32768, bsrc, 65536u, bm);
            }
        }
        // A: 128 channels per row = 2 K64 sub-tiles, 2 x 16B cp.async each
        int idx = nidx[axis_p * 3 + (h >> 1)];
        uint32_t sz = (idx >= 0) ? 16u : 0u;
        const char* arowp = reinterpret_cast<const char*>(g_featsBf) +
                            (size_t)(idx < 0 ? 0 : idx) * 512;
        uint32_t bo = (uint32_t)(arow * 128 + aseg * 32);
#pragma unroll
        for (int sub = 0; sub < 2; sub++) {
            int cidx = 2 * h + sub;
            const char* asrc = arowp + (size_t)(((cidx & 3) << 6) << 1) + aseg * 32;
            uint32_t adst = a_base + (uint32_t)sub * 16384;
            CP_ASYNC16(adst + SW128(bo), asrc, sz);
            CP_ASYNC16(adst + SW128(bo + 16), asrc + 16, sz);
        }
        CP_COMMIT();
    };

    // prime 1 chunk (stage depth 2, lag 1)
    produce(0);

    for (int g = 0; g < NMACRO; g++) {
        int axis_g = g / 6;
        int hax = g - axis_g * 6;
        int st = g & 1;
        int ph = (g >> 1) & 1;

        // retire chunk g's A group (exactly 1 pending at this point)
        CP_WAIT_GROUP(0);
        FENCE_PROXY_ASYNC();
        __syncthreads();

        // MMA issue first (8 x K16 dispatches), then produce next
        if (warp == 0) {
            if (elect_one()) {
                MBARRIER_WAIT_PARITY(sb + SMEM_BFULL + 8 * st, ph);
                if (hax == 0) TCGEN05_FENCE_AFTER();
                uint32_t a_base = sb + SMEM_STAGE + (uint32_t)st * STAGE_BYTES;
#pragma unroll
                for (int kk = 0; kk < 8; kk++) {
                    int sub = kk >> 2;
                    int k = kk & 3;
                    uint64_t ad = MAKE_SMEM_DESC(a_base + sub * 16384) + k * 2;
                    uint64_t bd = MAKE_SMEM_DESC(a_base + 32768 + sub * 32768) + k * 2;
                    mma_f16_ss(tmem, ad, bd, MMA_IDESC,
                               (uint32_t)((hax > 0) || (kk > 0)));
                }
                TCGEN05_COMMIT(sb + SMEM_FREE + 8 * st);
            }
        }

        if (g + 1 < NMACRO) produce(g + 1);

        if (hax == 5) {
            // axis complete: wait last MMA, BN+sigmoid accumulate
            MBARRIER_WAIT_PARITY(sb + SMEM_FREE + 8 * st, ph);
            TCGEN05_FENCE_AFTER();
            const float* gptr = gb + axis_g * 512;
#pragma unroll
            for (int i = 0; i < 4; i++) {
                uint32_t t[16];
                TCGEN05_LD_32X32B_X16(t, tmem + colb + i * 16);
                TCGEN05_WAIT_LD();
#pragma unroll
                for (int j = 0; j < 16; j++) {
                    int c = colb + i * 16 + j;
                    float y = __uint_as_float(t[j]);
                    float v = fmaf(y, gptr[c] * RS, gptr[256 + c]);
                    s[i * 16 + j] += 1.0f / (1.0f + __expf(-v));
                }
            }
            TCGEN05_FENCE_BEFORE();
            __syncthreads();   // TMEM reads done before next axis overwrites D
        }
    }

    // final: out = s * feats (fp32)
    if (egm < NVOX) {
        const float4* fr = reinterpret_cast<const float4*>(
            feats + (size_t)egm * CCH + colb);
        float4* orow = reinterpret_cast<float4*>(
            out + (size_t)egm * CCH + colb);
#pragma unroll
        for (int i = 0; i < 16; i++) {
            float4 f = fr[i];
            float4 r;
            r.x = f.x * s[i * 4 + 0];
            r.y = f.y * s[i * 4 + 1];
            r.z = f.z * s[i * 4 + 2];
            r.w = f.w * s[i * 4 + 3];
            orow[i] = r;
        }
    }
    __syncthreads();
    if (warp == 0) {
        TCGEN05_RELINQUISH();
        TCGEN05_DEALLOC(tmem, 256);
    }

#else
    // ------------------------------------------------------------------
    // Portable FP32 fallback (non-"a" PTX pass only)
    // ------------------------------------------------------------------
    float* a_tile = reinterpret_cast<float*>(smem);            // [128][65]
    float* w_tile = reinterpret_cast<float*>(smem + 33280);    // [64][256]

    for (int axis = 0; axis < 3; axis++) {
        const int* nb = (axis == 0) ? nx : ((axis == 1) ? ny : nz);
        const float* w = (axis == 0) ? w1 : ((axis == 1) ? w2 : w3);
        const float* gg = (axis == 0) ? g1 : ((axis == 1) ? g2 : g3);
        const float* bb = (axis == 0) ? b1 : ((axis == 1) ? b2 : b3);

        float y[64];
#pragma unroll
        for (int i = 0; i < 64; i++) y[i] = 0.0f;

        for (int tap = 0; tap < 3; tap++) {
            int idx = rowvalid ? __ldg(&nb[agm * 3 + tap]) : -1;
            for (int kc = 0; kc < 4; kc++) {
                int kbase = kc * 64;
                {
                    float v[16];
                    if (idx >= 0) {
                        const float4* src = reinterpret_cast<const float4*>(
                            feats + (size_t)idx * CCH + kbase + aseg * 16);
#pragma unroll
                        for (int i = 0; i < 4; i++) {
                            float4 f = src[i];
                            v[i * 4 + 0] = f.x; v[i * 4 + 1] = f.y;
                            v[i * 4 + 2] = f.z; v[i * 4 + 3] = f.w;
                        }
                    } else {
#pragma unroll
                        for (int i = 0; i < 16; i++) v[i] = 0.0f;
                    }
#pragma unroll
                    for (int i = 0; i < 16; i++)
                        a_tile[arow * 65 + aseg * 16 + i] = v[i];
                }
                {
                    const float4* src = reinterpret_cast<const float4*>(
                        w + (size_t)tap * 65536 + (size_t)kbase * 256);
                    float4* dst = reinterpret_cast<float4*>(w_tile);
#pragma unroll
                    for (int i = 0; i < 8; i++) dst[tid + i * 512] = src[tid + i * 512];
                }
                __syncthreads();
                for (int k = 0; k < 64; k++) {
                    float ra = a_tile[erow * 65 + k];
                    const float4* wr = reinterpret_cast<const float4*>(
                        w_tile + k * 256 + colb);
#pragma unroll
                    for (int cc = 0; cc < 16; cc++) {
                        float4 wv = wr[cc];
                        y[cc * 4 + 0] = fmaf(ra, wv.x, y[cc * 4 + 0]);
                        y[cc * 4 + 1] = fmaf(ra, wv.y, y[cc * 4 + 1]);
                        y[cc * 4 + 2] = fmaf(ra, wv.z, y[cc * 4 + 2]);
                        y[cc * 4 + 3] = fmaf(ra, wv.w, y[cc * 4 + 3]);
                    }
                }
                __syncthreads();
            }
        }
#pragma unroll
        for (int i = 0; i < 64; i++) {
            int c = colb + i;
            float v = fmaf(y[i], __ldg(&gg[c]) * RS, __ldg(&bb[c]));
            s[i] += 1.0f / (1.0f + __expf(-v));
        }
    }

    if (egm < NVOX) {
        const float4* fr = reinterpret_cast<const float4*>(
            feats + (size_t)egm * CCH + colb);
        float4* orow = reinterpret_cast<float4*>(
            out + (size_t)egm * CCH + colb);
#pragma unroll
        for (int i = 0; i < 16; i++) {
            float4 f = fr[i];
            float4 r;
            r.x = f.x * s[i * 4 + 0];
            r.y = f.y * s[i * 4 + 1];
            r.z = f.z * s[i * 4 + 2];
            r.w = f.w * s[i * 4 + 3];
            orow[i] = r;
        }
    }
#endif  // TC_OK
}

// ============================================================================
// Launch
// ============================================================================
extern "C" void kernel_launch(void* const* d_in, const int* in_sizes, int n_in,
                              void* d_out, int out_size) {
    const float* feats = (const float*)d_in[0];
    const float* w1 = (const float*)d_in[1];
    const float* w2 = (const float*)d_in[2];
    const float* w3 = (const float*)d_in[3];
    const float* g1 = (const float*)d_in[4];
    const float* b1 = (const float*)d_in[5];
    const float* g2 = (const float*)d_in[6];
    const float* b2 = (const float*)d_in[7];
    const float* g3 = (const float*)d_in[8];
    const float* b3 = (const float*)d_in[9];
    const int* nx = (const int*)d_in[10];
    const int* ny = (const int*)d_in[11];
    const int* nz = (const int*)d_in[12];
    float* out = (float*)d_out;

    cudaFuncSetAttribute(recon_main_kernel,
                         cudaFuncAttributeMaxDynamicSharedMemorySize, SMEM_BYTES);

    prep_all_kernel<<<PREP_BLOCKS, 256>>>(w1, w2, w3, feats);
    recon_main_kernel<<<NTILES, 512, SMEM_BYTES>>>(feats, w1, w2, w3,
                                                   g1, b1, g2, b2, g3, b3,
                                                   nx, ny, nz, out);
}